// round 13
// baseline (speedup 1.0000x reference)
#include <cuda_runtime.h>
#include <cuda_bf16.h>

#define Bb 128
#define Nn 1024
#define DMdim 64
#define K2 2048   // S * Nn

// Scratch (no allocs): static device globals
__device__ __nv_bfloat16 g_yhi[(size_t)8192 * 2048];     // 32 MB
__device__ __nv_bfloat16 g_ahi[2 * 1024 * 1024];         // 4 MB
__device__ unsigned char g_gcT[(size_t)1024 * 16384];    // 16 MB swizzled gc tiles
__device__ float g_weff[128 * 68];
__device__ float g_beff[128];

// ---------------------------------------------------------------------------
__device__ __forceinline__ unsigned s2u(const void* p) {
    unsigned a;
    asm("{ .reg .u64 t; cvta.to.shared.u64 t, %1; cvt.u32.u64 %0, t; }"
        : "=r"(a) : "l"(p));
    return a;
}
#define CP16(dst, src) \
    asm volatile("cp.async.cg.shared.global [%0], [%1], 16;" :: "r"(dst), "l"(src))
#define CP_COMMIT() asm volatile("cp.async.commit_group;" ::: "memory")
#define STS16(addr, v) \
    asm volatile("st.shared.u16 [%0], %1;" :: "r"(addr), "h"(v))
#define STS64(addr, v) \
    asm volatile("st.shared.b64 [%0], %1;" :: "r"(addr), "l"(v))

__device__ __forceinline__ unsigned short bf16u(float f) {
    __nv_bfloat16 t = __float2bfloat16(f);
    return *(unsigned short*)&t;
}
__device__ __forceinline__ unsigned long long packu2(unsigned a, unsigned b) {
    unsigned long long r;
    asm("mov.b64 %0, {%1, %2};" : "=l"(r) : "r"(a), "r"(b));
    return r;
}

// packed f32x2 helpers (FFMA2 path)
__device__ __forceinline__ unsigned long long pack2(float a, float b) {
    unsigned long long r;
    asm("mov.b64 %0, {%1, %2};" : "=l"(r) : "f"(a), "f"(b));
    return r;
}
__device__ __forceinline__ unsigned long long bcast2(float a) {
    unsigned long long r;
    asm("mov.b64 %0, {%1, %1};" : "=l"(r) : "f"(a));
    return r;
}
__device__ __forceinline__ void ffma2(unsigned long long& d,
                                      unsigned long long a, unsigned long long b) {
    asm("fma.rn.f32x2 %0, %1, %2, %0;" : "+l"(d) : "l"(a), "l"(b));
}
__device__ __forceinline__ float2 unpack2(unsigned long long v) {
    float x, y;
    asm("mov.b64 {%0, %1}, %2;" : "=f"(x), "=f"(y) : "l"(v));
    return make_float2(x, y);
}

__device__ __forceinline__ void ldsm4(unsigned* r, unsigned addr) {
    asm volatile("ldmatrix.sync.aligned.m8n8.x4.shared.b16 {%0,%1,%2,%3}, [%4];"
                 : "=r"(r[0]), "=r"(r[1]), "=r"(r[2]), "=r"(r[3]) : "r"(addr));
}
__device__ __forceinline__ void ldsm4t(unsigned* r, unsigned addr) {
    asm volatile("ldmatrix.sync.aligned.m8n8.x4.trans.shared.b16 {%0,%1,%2,%3}, [%4];"
                 : "=r"(r[0]), "=r"(r[1]), "=r"(r[2]), "=r"(r[3]) : "r"(addr));
}
__device__ __forceinline__ void mma16816(float* c, const unsigned* a,
                                         unsigned b0, unsigned b1) {
    asm volatile(
        "mma.sync.aligned.m16n8k16.row.col.f32.bf16.bf16.f32 "
        "{%0,%1,%2,%3}, {%4,%5,%6,%7}, {%8,%9}, {%0,%1,%2,%3};"
        : "+f"(c[0]), "+f"(c[1]), "+f"(c[2]), "+f"(c[3])
        : "r"(a[0]), "r"(a[1]), "r"(a[2]), "r"(a[3]), "r"(b0), "r"(b1));
}

// ---------------------------------------------------------------------------
__global__ __launch_bounds__(256) void k_adj(const float* __restrict__ adj)
{
    int i = blockIdx.x * 256 + threadIdx.x;
    float4 v = ((const float4*)adj)[i];
    ((__nv_bfloat162*)g_ahi)[i * 2 + 0] = __halves2bfloat162(
        __float2bfloat16(v.x), __float2bfloat16(v.y));
    ((__nv_bfloat162*)g_ahi)[i * 2 + 1] = __halves2bfloat162(
        __float2bfloat16(v.z), __float2bfloat16(v.w));
}

// ---------------------------------------------------------------------------
__global__ __launch_bounds__(256) void k_weff(
    const float* __restrict__ W_in, const float* __restrict__ b_in,
    const float* __restrict__ W_gc)
{
    int i = blockIdx.x * 256 + threadIdx.x;
    if (blockIdx.x < 34) {
        int op = i / 68, cp = i - op * 68;
        const float* wg = W_gc + (op & 63) * 128 + (op >> 6) * 64;
        float s = 0.f;
#pragma unroll 8
        for (int c = 0; c < 64; c++) s = fmaf(wg[c], W_in[c * 68 + cp], s);
        g_weff[op * 68 + cp] = s;
    } else if (threadIdx.x < 128) {
        int op = threadIdx.x;
        const float* wg = W_gc + (op & 63) * 128 + (op >> 6) * 64;
        float s = 0.f;
#pragma unroll 8
        for (int c = 0; c < 64; c++) s = fmaf(wg[c], b_in[c], s);
        g_beff[op] = s;
    }
}

// ---------------------------------------------------------------------------
// k_y: FFMA2, 2 cols/thread, 2 chunks of 32 pairs (h traffic halved).
// ---------------------------------------------------------------------------
__global__ __launch_bounds__(128) void k_y(
    const float* __restrict__ x, const float* __restrict__ m,
    const float* __restrict__ u, const float* __restrict__ h)
{
    __shared__ unsigned long long WPs[68][64];
    __shared__ unsigned long long bep[64];
    for (int i = threadIdx.x; i < 68 * 64; i += 128) {
        int cp = i >> 6, p = i & 63;
        WPs[cp][p] = pack2(g_weff[(2 * p) * 68 + cp], g_weff[(2 * p + 1) * 68 + cp]);
    }
    if (threadIdx.x < 64)
        bep[threadIdx.x] = pack2(g_beff[2 * threadIdx.x], g_beff[2 * threadIdx.x + 1]);
    __syncthreads();

    int b = blockIdx.x >> 2;
    int n0 = (blockIdx.x & 3) * 256 + threadIdx.x * 2;

    for (int ch = 0; ch < 2; ch++) {
        int p0 = ch * 32;
        unsigned long long acc[32][2];
#pragma unroll
        for (int i = 0; i < 32; i++) {
            unsigned long long bv = bep[p0 + i];
            acc[i][0] = bv; acc[i][1] = bv;
        }

#define YACC(cp, ptr) do {                                                     \
        float2 _v = *(const float2*)(ptr);                                     \
        unsigned long long _v0 = bcast2(_v.x), _v1 = bcast2(_v.y);             \
        _Pragma("unroll")                                                      \
        for (int i = 0; i < 32; i++) {                                         \
            unsigned long long _wp = WPs[cp][p0 + i];                          \
            ffma2(acc[i][0], _wp, _v0);                                        \
            ffma2(acc[i][1], _wp, _v1);                                        \
        }                                                                      \
    } while (0)

        YACC(0, &x[b * 1024 + n0]);
        YACC(1, &m[b * 1024 + n0]);
        YACC(2, &u[b * 2048 + n0]);
        YACC(3, &u[b * 2048 + 1024 + n0]);
        for (int c = 0; c < 64; c++)
            YACC(4 + c, &h[(b * 64 + c) * 1024 + n0]);
#undef YACC

#pragma unroll
        for (int i = 0; i < 32; i++) {
            float2 c0 = unpack2(acc[i][0]);
            float2 c1 = unpack2(acc[i][1]);
#pragma unroll
            for (int q = 0; q < 2; q++) {
                int op = ch * 64 + 2 * i + q;
                float v0 = q ? c0.y : c0.x;
                float v1 = q ? c1.y : c1.x;
                int s = op >> 6, oc = op & 63;
                size_t yi = (size_t)(b * 64 + oc) * K2 + s * 1024 + n0;
                __nv_bfloat162 hp = __halves2bfloat162(
                    __float2bfloat16(v0), __float2bfloat16(v1));
                *(unsigned*)&g_yhi[yi] = *(unsigned*)&hp;
            }
        }
    }
}

// ---------------------------------------------------------------------------
// GEMM (unchanged from R12 — proven): single-pass bf16 mma.sync -> gcT tiles
// ---------------------------------------------------------------------------
#define BM 128
#define BN 128
#define BK 64
#define ASTG (128 * 128)
#define STGB (2 * ASTG)
#define GDYN (3 * STGB)
#define NCHK 32

__device__ __forceinline__ void load_chunk(unsigned base, int st, int t,
                                           int bm, int bn, int tid)
{
    int k0 = t * BK;
    int s = k0 >> 10;
    int v0 = k0 & 1023;
    unsigned ab = base + st * STGB;
    unsigned bb = ab + ASTG;
#pragma unroll
    for (int i = 0; i < 8; i++) {
        int u2 = tid + i * 128;
        int row = u2 >> 3, j = u2 & 7;
        CP16(ab + row * 128 + ((j ^ (row & 7)) * 16),
             (const char*)(g_yhi + (size_t)(bm + row) * K2 + k0 + j * 8));
    }
#pragma unroll
    for (int i = 0; i < 8; i++) {
        int u2 = tid + i * 128;
        int row = u2 >> 3, j = u2 & 7;
        CP16(bb + row * 128 + ((j ^ (row & 7)) * 16),
             (const char*)(g_ahi + (size_t)s * 1048576 +
                           (size_t)(bn + row) * 1024 + v0 + j * 8));
    }
    CP_COMMIT();
}

__global__ __launch_bounds__(128, 2) void k_gemm_mma(const float* __restrict__ b_gc)
{
    extern __shared__ __align__(16) char dsm[];
    unsigned base = s2u(dsm);

    int tid = threadIdx.x;
    int lane = tid & 31;
    int wid = tid >> 5;
    int wm = wid >> 1;
    int wn = wid & 1;
    int bm = blockIdx.y * BM;
    int bn = blockIdx.x * BN;

    float acc[4][8][4];
#pragma unroll
    for (int i = 0; i < 4; i++)
#pragma unroll
        for (int j = 0; j < 8; j++)
#pragma unroll
            for (int q = 0; q < 4; q++) acc[i][j][q] = 0.f;

    load_chunk(base, 0, 0, bm, bn, tid);
    load_chunk(base, 1, 1, bm, bn, tid);

    int st = 0;
    for (int t = 0; t < NCHK; t++) {
        if (t == NCHK - 1) asm volatile("cp.async.wait_group 0;" ::: "memory");
        else               asm volatile("cp.async.wait_group 1;" ::: "memory");
        __syncthreads();

        if (t + 2 < NCHK) {
            int st2 = st + 2; if (st2 >= 3) st2 -= 3;
            load_chunk(base, st2, t + 2, bm, bn, tid);
        }

        unsigned abuf = base + st * STGB;
        unsigned bbuf = abuf + ASTG;

#pragma unroll
        for (int kk = 0; kk < 4; kk++) {
            unsigned ar[4][4];
#pragma unroll
            for (int mf = 0; mf < 4; mf++) {
                int mrow = wm * 64 + mf * 16 + (lane & 7) + ((lane >> 3) & 1) * 8;
                int uidx = kk * 2 + (lane >> 4);
                ldsm4(ar[mf], abuf + mrow * 128 + ((uidx ^ (mrow & 7)) * 16));
            }
            unsigned br[4][4];
#pragma unroll
            for (int nt = 0; nt < 4; nt++) {
                int nrow = wn * 64 + nt * 16 + (lane & 7) + (lane >> 4) * 8;
                int uidx = kk * 2 + ((lane >> 3) & 1);
                ldsm4(br[nt], bbuf + nrow * 128 + ((uidx ^ (nrow & 7)) * 16));
            }
#pragma unroll
            for (int mf = 0; mf < 4; mf++)
#pragma unroll
                for (int nt = 0; nt < 4; nt++) {
                    mma16816(acc[mf][nt * 2 + 0], ar[mf], br[nt][0], br[nt][1]);
                    mma16816(acc[mf][nt * 2 + 1], ar[mf], br[nt][2], br[nt][3]);
                }
        }
        st++; if (st >= 3) st = 0;
    }

#pragma unroll
    for (int mf = 0; mf < 4; mf++) {
        int r0 = bm + wm * 64 + mf * 16 + (lane >> 2);
#pragma unroll
        for (int nf = 0; nf < 8; nf++) {
            int col = bn + wn * 64 + nf * 8 + (lane & 3) * 2;
            int nt_ = col & 127;
            float* c4 = acc[mf][nf];
#pragma unroll
            for (int rr = 0; rr < 2; rr++) {
                int mrow = r0 + rr * 8;
                int bI = mrow >> 6, o = mrow & 63;
                float bias = __ldg(&b_gc[o]);
                __nv_bfloat162 pv = __halves2bfloat162(
                    __float2bfloat16(c4[rr * 2 + 0] + bias),
                    __float2bfloat16(c4[rr * 2 + 1] + bias));
                size_t off = (size_t)(bI * 8 + (col >> 7)) * 16384 +
                             o * 256 + (((nt_ >> 3) ^ (o & 7)) * 16) + (nt_ & 7) * 2;
                *(unsigned*)(g_gcT + off) = *(unsigned*)&pv;
            }
        }
    }
}

// ---------------------------------------------------------------------------
// k_out_mma v3: h-copy fused into staging; readout split across 256 threads.
// ---------------------------------------------------------------------------
#define ODYN 81920

__global__ __launch_bounds__(256, 2) void k_out_mma(
    const float* __restrict__ h, const float* __restrict__ W_out,
    const float* __restrict__ b_out, const float* __restrict__ W_read,
    const float* __restrict__ b_read, const float* __restrict__ prelu_w,
    float* __restrict__ out)
{
    extern __shared__ __align__(16) char dsm[];
    unsigned As = s2u(dsm);
    unsigned gcA = As + 32768;
    unsigned hA = As + 49152;
    float* prelu_s = (float*)dsm;

    __shared__ float Wr_s[128];
    __shared__ float bo_s[64];
    __shared__ float rpart[256];

    int tid = threadIdx.x;
    int lane = tid & 31;
    int wid = tid >> 5;
    int b = blockIdx.x >> 3;
    int n0 = (blockIdx.x & 7) * 128;
    float* out2 = out + (size_t)Bb * Nn;

    // gc tile via cp.async
    const char* gsrc = (const char*)g_gcT + (size_t)blockIdx.x * 16384;
#pragma unroll
    for (int i = 0; i < 4; i++) {
        int u = tid + i * 256;
        CP16(gcA + u * 16, gsrc + u * 16);
    }
    CP_COMMIT();

    if (tid < 128) Wr_s[tid] = W_read[tid];
    if (tid >= 128 && tid < 192) bo_s[tid - 128] = b_out[tid - 128];

    // ---- stage h (hi/lo) + fused exact h copy to out2 ----
#pragma unroll
    for (int i = 0; i < 8; i++) {
        int u = tid + i * 256;
        int c = u >> 5, nf4 = u & 31, n = nf4 * 4;
        float4 hv = *(const float4*)&h[(size_t)(b * 64 + c) * 1024 + n0 + n];
        *(float4*)&out2[(size_t)(b * 128 + 64 + c) * 1024 + n0 + n] = hv;
        __nv_bfloat16 h0 = __float2bfloat16(hv.x);
        __nv_bfloat16 h1 = __float2bfloat16(hv.y);
        __nv_bfloat16 h2 = __float2bfloat16(hv.z);
        __nv_bfloat16 h3 = __float2bfloat16(hv.w);
        __nv_bfloat162 hp0 = __halves2bfloat162(h0, h1);
        __nv_bfloat162 hp1 = __halves2bfloat162(h2, h3);
        unsigned long long hip = packu2(*(unsigned*)&hp0, *(unsigned*)&hp1);
        __nv_bfloat162 lp0 = __halves2bfloat162(
            __float2bfloat16(hv.x - __bfloat162float(h0)),
            __float2bfloat16(hv.y - __bfloat162float(h1)));
        __nv_bfloat162 lp1 = __halves2bfloat162(
            __float2bfloat16(hv.z - __bfloat162float(h2)),
            __float2bfloat16(hv.w - __bfloat162float(h3)));
        unsigned long long lop = packu2(*(unsigned*)&lp0, *(unsigned*)&lp1);
        unsigned sw = (((n >> 3) ^ (c & 7)) * 16) + (n & 7) * 2;
        STS64(hA + c * 256 + sw, hip);
        STS64(hA + (c + 64) * 256 + sw, lop);
    }
    // ---- stage A: W_out [64 o][k192] rows 512B ----
#pragma unroll
    for (int i = 0; i < 8; i++) {
        int u = tid + i * 256;
        int o = u >> 5, f4 = u & 31;
        float4 w = *(const float4*)&W_out[o * 128 + f4 * 4];
        float vv[4] = {w.x, w.y, w.z, w.w};
        unsigned rowa = As + o * 512;
        unsigned x7 = (o & 7);
#pragma unroll
        for (int j = 0; j < 4; j++) {
            int c = f4 * 4 + j;
            if (c < 64) {
                STS16(rowa + (((c >> 3) ^ x7) * 16) + (c & 7) * 2, bf16u(vv[j]));
            } else {
                __nv_bfloat16 hb = __float2bfloat16(vv[j]);
                unsigned short hu = *(unsigned short*)&hb;
                unsigned short lu = bf16u(vv[j] - __bfloat162float(hb));
                int k1 = c;
                int k2 = c + 64;
                STS16(rowa + (((k1 >> 3) ^ x7) * 16) + (k1 & 7) * 2, hu);
                STS16(rowa + (((k2 >> 3) ^ x7) * 16) + (k2 & 7) * 2, lu);
            }
        }
    }
    asm volatile("cp.async.wait_group 0;" ::: "memory");
    __syncthreads();

    // ---- mma: M=64 N=128, 16 k16-steps ----
    int wm = wid >> 1;
    int wn = wid & 1;
    float acc[8][4];
#pragma unroll
    for (int j = 0; j < 8; j++)
#pragma unroll
        for (int q = 0; q < 4; q++) acc[j][q] = 0.f;

#pragma unroll
    for (int kk = 0; kk < 16; kk++) {
        int akk = (kk < 8) ? kk : kk - 4;
        unsigned ar[4];
        int mrow = wm * 16 + (lane & 7) + ((lane >> 3) & 1) * 8;
        int uA = akk * 2 + (lane >> 4);
        ldsm4(ar, As + mrow * 512 + ((uA ^ (mrow & 7)) * 16));

        unsigned barea; int kbase;
        if (kk < 4)       { barea = gcA; kbase = kk * 16; }
        else if (kk < 8)  { barea = hA;  kbase = (kk - 4) * 16; }
        else if (kk < 12) { barea = hA;  kbase = 64 + (kk - 8) * 16; }
        else              { barea = hA;  kbase = (kk - 12) * 16; }
        int kr = kbase + (lane & 7) + ((lane >> 3) & 1) * 8;

        unsigned br[4][4];
#pragma unroll
        for (int nt = 0; nt < 4; nt++) {
            int nu = ((wn * 64 + nt * 16) >> 3) + (lane >> 4);
            ldsm4t(br[nt], barea + kr * 256 + ((nu ^ (kr & 7)) * 16));
        }
#pragma unroll
        for (int nt = 0; nt < 4; nt++) {
            mma16816(acc[nt * 2 + 0], ar, br[nt][0], br[nt][1]);
            mma16816(acc[nt * 2 + 1], ar, br[nt][2], br[nt][3]);
        }
    }
    __syncthreads();   // smem reads done; safe to overwrite with prelu_s

    // ---- epilogue: bias + PReLU -> out2 + prelu_s ----
    float pw = __ldg(prelu_w);
    int o0 = wm * 16 + (lane >> 2);
    float b0v = bo_s[o0];
    float b1v = bo_s[o0 + 8];
#pragma unroll
    for (int nt = 0; nt < 4; nt++)
#pragma unroll
        for (int q = 0; q < 2; q++) {
            int ncol = wn * 64 + nt * 16 + q * 8 + (lane & 3) * 2;
            float* c4 = acc[nt * 2 + q];
            float v0 = c4[0] + b0v, v1 = c4[1] + b0v;
            float v2 = c4[2] + b1v, v3 = c4[3] + b1v;
            float p0 = v0 >= 0.f ? v0 : pw * v0;
            float p1 = v1 >= 0.f ? v1 : pw * v1;
            float p2 = v2 >= 0.f ? v2 : pw * v2;
            float p3 = v3 >= 0.f ? v3 : pw * v3;
            *(float2*)&out2[(size_t)(b * 128 + o0) * 1024 + n0 + ncol] =
                make_float2(p0, p1);
            *(float2*)&out2[(size_t)(b * 128 + o0 + 8) * 1024 + n0 + ncol] =
                make_float2(p2, p3);
            *(float2*)&prelu_s[o0 * 132 + ncol] = make_float2(p0, p1);
            *(float2*)&prelu_s[(o0 + 8) * 132 + ncol] = make_float2(p2, p3);
        }
    __syncthreads();

    // ---- readout conv: 256 threads, 2-way split over channels ----
    {
        int n = tid & 127;
        int half = tid >> 7;
        float r = 0.f;
        if (half == 0) {
            r = __ldg(b_read);
            for (int o = 0; o < 64; o++)
                r = fmaf(Wr_s[o], prelu_s[o * 132 + n], r);
        } else {
            for (int c = 0; c < 64; c++)
                r = fmaf(Wr_s[64 + c],
                         h[(size_t)(b * 64 + c) * 1024 + n0 + n], r);
        }
        rpart[half * 128 + n] = r;
    }
    __syncthreads();
    if (tid < 128)
        out[(size_t)b * 1024 + n0 + tid] = rpart[tid] + rpart[128 + tid];
}

// ---------------------------------------------------------------------------
extern "C" void kernel_launch(void* const* d_in, const int* in_sizes, int n_in,
                              void* d_out, int out_size)
{
    const float* x      = (const float*)d_in[0];
    const float* m      = (const float*)d_in[1];
    const float* u      = (const float*)d_in[2];
    const float* h      = (const float*)d_in[3];
    const float* adj    = (const float*)d_in[4];
    const float* W_in   = (const float*)d_in[5];
    const float* b_in   = (const float*)d_in[6];
    const float* W_gc   = (const float*)d_in[7];
    const float* b_gc   = (const float*)d_in[8];
    const float* W_out  = (const float*)d_in[9];
    const float* b_out  = (const float*)d_in[10];
    const float* W_read = (const float*)d_in[11];
    const float* b_read = (const float*)d_in[12];
    const float* prelu  = (const float*)d_in[13];
    float* out = (float*)d_out;

    cudaFuncSetAttribute(k_gemm_mma, cudaFuncAttributeMaxDynamicSharedMemorySize, GDYN);
    cudaFuncSetAttribute(k_out_mma, cudaFuncAttributeMaxDynamicSharedMemorySize, ODYN);

    k_adj<<<2048, 256>>>(adj);
    k_weff<<<35, 256>>>(W_in, b_in, W_gc);
    k_y<<<512, 128>>>(x, m, u, h);
    dim3 g(Nn / BN, (Bb * DMdim) / BM);   // (8, 64) = 512 CTAs
    k_gemm_mma<<<g, 128, GDYN>>>(b_gc);
    k_out_mma<<<1024, 256, ODYN>>>(h, W_out, b_out, W_read, b_read, prelu, out);
}

// round 14
// speedup vs baseline: 1.2416x; 1.2416x over previous
#include <cuda_runtime.h>
#include <cuda_bf16.h>

#define Bb 128
#define Nn 1024
#define DMdim 64
#define K2 2048   // S * Nn

// Scratch (no allocs): static device globals
__device__ __nv_bfloat16 g_yhi[(size_t)8192 * 2048];     // 32 MB
__device__ __nv_bfloat16 g_ahi[2 * 1024 * 1024];         // 4 MB
__device__ unsigned char g_gcT[(size_t)1024 * 16384];    // 16 MB swizzled gc tiles
__device__ float g_weff[128 * 68];
__device__ float g_beff[128];

// ---------------------------------------------------------------------------
__device__ __forceinline__ unsigned s2u(const void* p) {
    unsigned a;
    asm("{ .reg .u64 t; cvta.to.shared.u64 t, %1; cvt.u32.u64 %0, t; }"
        : "=r"(a) : "l"(p));
    return a;
}
#define CP16(dst, src) \
    asm volatile("cp.async.cg.shared.global [%0], [%1], 16;" :: "r"(dst), "l"(src))
#define CP_COMMIT() asm volatile("cp.async.commit_group;" ::: "memory")
#define STS16(addr, v) \
    asm volatile("st.shared.u16 [%0], %1;" :: "r"(addr), "h"(v))
#define STS64(addr, v) \
    asm volatile("st.shared.b64 [%0], %1;" :: "r"(addr), "l"(v))

__device__ __forceinline__ unsigned short bf16u(float f) {
    __nv_bfloat16 t = __float2bfloat16(f);
    return *(unsigned short*)&t;
}
__device__ __forceinline__ unsigned long long packu2(unsigned a, unsigned b) {
    unsigned long long r;
    asm("mov.b64 %0, {%1, %2};" : "=l"(r) : "r"(a), "r"(b));
    return r;
}

// packed f32x2 helpers (FFMA2 path)
__device__ __forceinline__ unsigned long long pack2(float a, float b) {
    unsigned long long r;
    asm("mov.b64 %0, {%1, %2};" : "=l"(r) : "f"(a), "f"(b));
    return r;
}
__device__ __forceinline__ unsigned long long bcast2(float a) {
    unsigned long long r;
    asm("mov.b64 %0, {%1, %1};" : "=l"(r) : "f"(a));
    return r;
}
__device__ __forceinline__ void ffma2(unsigned long long& d,
                                      unsigned long long a, unsigned long long b) {
    asm("fma.rn.f32x2 %0, %1, %2, %0;" : "+l"(d) : "l"(a), "l"(b));
}
__device__ __forceinline__ float2 unpack2(unsigned long long v) {
    float x, y;
    asm("mov.b64 {%0, %1}, %2;" : "=f"(x), "=f"(y) : "l"(v));
    return make_float2(x, y);
}

__device__ __forceinline__ void ldsm4(unsigned* r, unsigned addr) {
    asm volatile("ldmatrix.sync.aligned.m8n8.x4.shared.b16 {%0,%1,%2,%3}, [%4];"
                 : "=r"(r[0]), "=r"(r[1]), "=r"(r[2]), "=r"(r[3]) : "r"(addr));
}
__device__ __forceinline__ void ldsm4t(unsigned* r, unsigned addr) {
    asm volatile("ldmatrix.sync.aligned.m8n8.x4.trans.shared.b16 {%0,%1,%2,%3}, [%4];"
                 : "=r"(r[0]), "=r"(r[1]), "=r"(r[2]), "=r"(r[3]) : "r"(addr));
}
__device__ __forceinline__ void mma16816(float* c, const unsigned* a,
                                         unsigned b0, unsigned b1) {
    asm volatile(
        "mma.sync.aligned.m16n8k16.row.col.f32.bf16.bf16.f32 "
        "{%0,%1,%2,%3}, {%4,%5,%6,%7}, {%8,%9}, {%0,%1,%2,%3};"
        : "+f"(c[0]), "+f"(c[1]), "+f"(c[2]), "+f"(c[3])
        : "r"(a[0]), "r"(a[1]), "r"(a[2]), "r"(a[3]), "r"(b0), "r"(b1));
}

// ---------------------------------------------------------------------------
__global__ __launch_bounds__(256) void k_adj(const float* __restrict__ adj)
{
    int i = blockIdx.x * 256 + threadIdx.x;
    float4 v = ((const float4*)adj)[i];
    ((__nv_bfloat162*)g_ahi)[i * 2 + 0] = __halves2bfloat162(
        __float2bfloat16(v.x), __float2bfloat16(v.y));
    ((__nv_bfloat162*)g_ahi)[i * 2 + 1] = __halves2bfloat162(
        __float2bfloat16(v.z), __float2bfloat16(v.w));
}

// ---------------------------------------------------------------------------
__global__ __launch_bounds__(256) void k_weff(
    const float* __restrict__ W_in, const float* __restrict__ b_in,
    const float* __restrict__ W_gc)
{
    int i = blockIdx.x * 256 + threadIdx.x;
    if (blockIdx.x < 34) {
        int op = i / 68, cp = i - op * 68;
        const float* wg = W_gc + (op & 63) * 128 + (op >> 6) * 64;
        float s = 0.f;
#pragma unroll 8
        for (int c = 0; c < 64; c++) s = fmaf(wg[c], W_in[c * 68 + cp], s);
        g_weff[op * 68 + cp] = s;
    } else if (threadIdx.x < 128) {
        int op = threadIdx.x;
        const float* wg = W_gc + (op & 63) * 128 + (op >> 6) * 64;
        float s = 0.f;
#pragma unroll 8
        for (int c = 0; c < 64; c++) s = fmaf(wg[c], b_in[c], s);
        g_beff[op] = s;
    }
}

// ---------------------------------------------------------------------------
// k_y (R12-proven): FFMA2, 2 cols/thread, 4 chunks of 16 pairs,
// 512 blocks x 128 thr. Low register pressure = high occupancy; h re-reads
// are L2 hits.
// ---------------------------------------------------------------------------
__global__ __launch_bounds__(128) void k_y(
    const float* __restrict__ x, const float* __restrict__ m,
    const float* __restrict__ u, const float* __restrict__ h)
{
    __shared__ unsigned long long WPs[68][64];
    __shared__ unsigned long long bep[64];
    for (int i = threadIdx.x; i < 68 * 64; i += 128) {
        int cp = i >> 6, p = i & 63;
        WPs[cp][p] = pack2(g_weff[(2 * p) * 68 + cp], g_weff[(2 * p + 1) * 68 + cp]);
    }
    if (threadIdx.x < 64)
        bep[threadIdx.x] = pack2(g_beff[2 * threadIdx.x], g_beff[2 * threadIdx.x + 1]);
    __syncthreads();

    int b = blockIdx.x >> 2;
    int n0 = (blockIdx.x & 3) * 256 + threadIdx.x * 2;

    for (int ch = 0; ch < 4; ch++) {
        int p0 = ch * 16;
        unsigned long long acc[16][2];
#pragma unroll
        for (int i = 0; i < 16; i++) {
            unsigned long long bv = bep[p0 + i];
            acc[i][0] = bv; acc[i][1] = bv;
        }

#define YACC(cp, ptr) do {                                                     \
        float2 _v = *(const float2*)(ptr);                                     \
        unsigned long long _v0 = bcast2(_v.x), _v1 = bcast2(_v.y);             \
        _Pragma("unroll")                                                      \
        for (int i = 0; i < 16; i++) {                                         \
            unsigned long long _wp = WPs[cp][p0 + i];                          \
            ffma2(acc[i][0], _wp, _v0);                                        \
            ffma2(acc[i][1], _wp, _v1);                                        \
        }                                                                      \
    } while (0)

        YACC(0, &x[b * 1024 + n0]);
        YACC(1, &m[b * 1024 + n0]);
        YACC(2, &u[b * 2048 + n0]);
        YACC(3, &u[b * 2048 + 1024 + n0]);
        for (int c = 0; c < 64; c++)
            YACC(4 + c, &h[(b * 64 + c) * 1024 + n0]);
#undef YACC

#pragma unroll
        for (int i = 0; i < 16; i++) {
            float2 c0 = unpack2(acc[i][0]);
            float2 c1 = unpack2(acc[i][1]);
#pragma unroll
            for (int q = 0; q < 2; q++) {
                int op = ch * 32 + 2 * i + q;
                float v0 = q ? c0.y : c0.x;
                float v1 = q ? c1.y : c1.x;
                int s = op >> 6, oc = op & 63;
                size_t yi = (size_t)(b * 64 + oc) * K2 + s * 1024 + n0;
                __nv_bfloat162 hp = __halves2bfloat162(
                    __float2bfloat16(v0), __float2bfloat16(v1));
                *(unsigned*)&g_yhi[yi] = *(unsigned*)&hp;
            }
        }
    }
}

// ---------------------------------------------------------------------------
// GEMM (unchanged — proven): single-pass bf16 mma.sync -> gcT tiles
// ---------------------------------------------------------------------------
#define BM 128
#define BN 128
#define BK 64
#define ASTG (128 * 128)
#define STGB (2 * ASTG)
#define GDYN (3 * STGB)
#define NCHK 32

__device__ __forceinline__ void load_chunk(unsigned base, int st, int t,
                                           int bm, int bn, int tid)
{
    int k0 = t * BK;
    int s = k0 >> 10;
    int v0 = k0 & 1023;
    unsigned ab = base + st * STGB;
    unsigned bb = ab + ASTG;
#pragma unroll
    for (int i = 0; i < 8; i++) {
        int u2 = tid + i * 128;
        int row = u2 >> 3, j = u2 & 7;
        CP16(ab + row * 128 + ((j ^ (row & 7)) * 16),
             (const char*)(g_yhi + (size_t)(bm + row) * K2 + k0 + j * 8));
    }
#pragma unroll
    for (int i = 0; i < 8; i++) {
        int u2 = tid + i * 128;
        int row = u2 >> 3, j = u2 & 7;
        CP16(bb + row * 128 + ((j ^ (row & 7)) * 16),
             (const char*)(g_ahi + (size_t)s * 1048576 +
                           (size_t)(bn + row) * 1024 + v0 + j * 8));
    }
    CP_COMMIT();
}

__global__ __launch_bounds__(128, 2) void k_gemm_mma(const float* __restrict__ b_gc)
{
    extern __shared__ __align__(16) char dsm[];
    unsigned base = s2u(dsm);

    int tid = threadIdx.x;
    int lane = tid & 31;
    int wid = tid >> 5;
    int wm = wid >> 1;
    int wn = wid & 1;
    int bm = blockIdx.y * BM;
    int bn = blockIdx.x * BN;

    float acc[4][8][4];
#pragma unroll
    for (int i = 0; i < 4; i++)
#pragma unroll
        for (int j = 0; j < 8; j++)
#pragma unroll
            for (int q = 0; q < 4; q++) acc[i][j][q] = 0.f;

    load_chunk(base, 0, 0, bm, bn, tid);
    load_chunk(base, 1, 1, bm, bn, tid);

    int st = 0;
    for (int t = 0; t < NCHK; t++) {
        if (t == NCHK - 1) asm volatile("cp.async.wait_group 0;" ::: "memory");
        else               asm volatile("cp.async.wait_group 1;" ::: "memory");
        __syncthreads();

        if (t + 2 < NCHK) {
            int st2 = st + 2; if (st2 >= 3) st2 -= 3;
            load_chunk(base, st2, t + 2, bm, bn, tid);
        }

        unsigned abuf = base + st * STGB;
        unsigned bbuf = abuf + ASTG;

#pragma unroll
        for (int kk = 0; kk < 4; kk++) {
            unsigned ar[4][4];
#pragma unroll
            for (int mf = 0; mf < 4; mf++) {
                int mrow = wm * 64 + mf * 16 + (lane & 7) + ((lane >> 3) & 1) * 8;
                int uidx = kk * 2 + (lane >> 4);
                ldsm4(ar[mf], abuf + mrow * 128 + ((uidx ^ (mrow & 7)) * 16));
            }
            unsigned br[4][4];
#pragma unroll
            for (int nt = 0; nt < 4; nt++) {
                int nrow = wn * 64 + nt * 16 + (lane & 7) + (lane >> 4) * 8;
                int uidx = kk * 2 + ((lane >> 3) & 1);
                ldsm4(br[nt], bbuf + nrow * 128 + ((uidx ^ (nrow & 7)) * 16));
            }
#pragma unroll
            for (int mf = 0; mf < 4; mf++)
#pragma unroll
                for (int nt = 0; nt < 4; nt++) {
                    mma16816(acc[mf][nt * 2 + 0], ar[mf], br[nt][0], br[nt][1]);
                    mma16816(acc[mf][nt * 2 + 1], ar[mf], br[nt][2], br[nt][3]);
                }
        }
        st++; if (st >= 3) st = 0;
    }

#pragma unroll
    for (int mf = 0; mf < 4; mf++) {
        int r0 = bm + wm * 64 + mf * 16 + (lane >> 2);
#pragma unroll
        for (int nf = 0; nf < 8; nf++) {
            int col = bn + wn * 64 + nf * 8 + (lane & 3) * 2;
            int nt_ = col & 127;
            float* c4 = acc[mf][nf];
#pragma unroll
            for (int rr = 0; rr < 2; rr++) {
                int mrow = r0 + rr * 8;
                int bI = mrow >> 6, o = mrow & 63;
                float bias = __ldg(&b_gc[o]);
                __nv_bfloat162 pv = __halves2bfloat162(
                    __float2bfloat16(c4[rr * 2 + 0] + bias),
                    __float2bfloat16(c4[rr * 2 + 1] + bias));
                size_t off = (size_t)(bI * 8 + (col >> 7)) * 16384 +
                             o * 256 + (((nt_ >> 3) ^ (o & 7)) * 16) + (nt_ & 7) * 2;
                *(unsigned*)(g_gcT + off) = *(unsigned*)&pv;
            }
        }
    }
}

// ---------------------------------------------------------------------------
// k_out_mma v3 (kept from R13): fused h-copy, split readout.
// ---------------------------------------------------------------------------
#define ODYN 81920

__global__ __launch_bounds__(256, 2) void k_out_mma(
    const float* __restrict__ h, const float* __restrict__ W_out,
    const float* __restrict__ b_out, const float* __restrict__ W_read,
    const float* __restrict__ b_read, const float* __restrict__ prelu_w,
    float* __restrict__ out)
{
    extern __shared__ __align__(16) char dsm[];
    unsigned As = s2u(dsm);
    unsigned gcA = As + 32768;
    unsigned hA = As + 49152;
    float* prelu_s = (float*)dsm;

    __shared__ float Wr_s[128];
    __shared__ float bo_s[64];
    __shared__ float rpart[256];

    int tid = threadIdx.x;
    int lane = tid & 31;
    int wid = tid >> 5;
    int b = blockIdx.x >> 3;
    int n0 = (blockIdx.x & 7) * 128;
    float* out2 = out + (size_t)Bb * Nn;

    // gc tile via cp.async
    const char* gsrc = (const char*)g_gcT + (size_t)blockIdx.x * 16384;
#pragma unroll
    for (int i = 0; i < 4; i++) {
        int u = tid + i * 256;
        CP16(gcA + u * 16, gsrc + u * 16);
    }
    CP_COMMIT();

    if (tid < 128) Wr_s[tid] = W_read[tid];
    if (tid >= 128 && tid < 192) bo_s[tid - 128] = b_out[tid - 128];

    // ---- stage h (hi/lo) + fused exact h copy to out2 ----
#pragma unroll
    for (int i = 0; i < 8; i++) {
        int u = tid + i * 256;
        int c = u >> 5, nf4 = u & 31, n = nf4 * 4;
        float4 hv = *(const float4*)&h[(size_t)(b * 64 + c) * 1024 + n0 + n];
        *(float4*)&out2[(size_t)(b * 128 + 64 + c) * 1024 + n0 + n] = hv;
        __nv_bfloat16 h0 = __float2bfloat16(hv.x);
        __nv_bfloat16 h1 = __float2bfloat16(hv.y);
        __nv_bfloat16 h2 = __float2bfloat16(hv.z);
        __nv_bfloat16 h3 = __float2bfloat16(hv.w);
        __nv_bfloat162 hp0 = __halves2bfloat162(h0, h1);
        __nv_bfloat162 hp1 = __halves2bfloat162(h2, h3);
        unsigned long long hip = packu2(*(unsigned*)&hp0, *(unsigned*)&hp1);
        __nv_bfloat162 lp0 = __halves2bfloat162(
            __float2bfloat16(hv.x - __bfloat162float(h0)),
            __float2bfloat16(hv.y - __bfloat162float(h1)));
        __nv_bfloat162 lp1 = __halves2bfloat162(
            __float2bfloat16(hv.z - __bfloat162float(h2)),
            __float2bfloat16(hv.w - __bfloat162float(h3)));
        unsigned long long lop = packu2(*(unsigned*)&lp0, *(unsigned*)&lp1);
        unsigned sw = (((n >> 3) ^ (c & 7)) * 16) + (n & 7) * 2;
        STS64(hA + c * 256 + sw, hip);
        STS64(hA + (c + 64) * 256 + sw, lop);
    }
    // ---- stage A: W_out [64 o][k192] rows 512B ----
#pragma unroll
    for (int i = 0; i < 8; i++) {
        int u = tid + i * 256;
        int o = u >> 5, f4 = u & 31;
        float4 w = *(const float4*)&W_out[o * 128 + f4 * 4];
        float vv[4] = {w.x, w.y, w.z, w.w};
        unsigned rowa = As + o * 512;
        unsigned x7 = (o & 7);
#pragma unroll
        for (int j = 0; j < 4; j++) {
            int c = f4 * 4 + j;
            if (c < 64) {
                STS16(rowa + (((c >> 3) ^ x7) * 16) + (c & 7) * 2, bf16u(vv[j]));
            } else {
                __nv_bfloat16 hb = __float2bfloat16(vv[j]);
                unsigned short hu = *(unsigned short*)&hb;
                unsigned short lu = bf16u(vv[j] - __bfloat162float(hb));
                int k1 = c;
                int k2 = c + 64;
                STS16(rowa + (((k1 >> 3) ^ x7) * 16) + (k1 & 7) * 2, hu);
                STS16(rowa + (((k2 >> 3) ^ x7) * 16) + (k2 & 7) * 2, lu);
            }
        }
    }
    asm volatile("cp.async.wait_group 0;" ::: "memory");
    __syncthreads();

    // ---- mma: M=64 N=128, 16 k16-steps ----
    int wm = wid >> 1;
    int wn = wid & 1;
    float acc[8][4];
#pragma unroll
    for (int j = 0; j < 8; j++)
#pragma unroll
        for (int q = 0; q < 4; q++) acc[j][q] = 0.f;

#pragma unroll
    for (int kk = 0; kk < 16; kk++) {
        int akk = (kk < 8) ? kk : kk - 4;
        unsigned ar[4];
        int mrow = wm * 16 + (lane & 7) + ((lane >> 3) & 1) * 8;
        int uA = akk * 2 + (lane >> 4);
        ldsm4(ar, As + mrow * 512 + ((uA ^ (mrow & 7)) * 16));

        unsigned barea; int kbase;
        if (kk < 4)       { barea = gcA; kbase = kk * 16; }
        else if (kk < 8)  { barea = hA;  kbase = (kk - 4) * 16; }
        else if (kk < 12) { barea = hA;  kbase = 64 + (kk - 8) * 16; }
        else              { barea = hA;  kbase = (kk - 12) * 16; }
        int kr = kbase + (lane & 7) + ((lane >> 3) & 1) * 8;

        unsigned br[4][4];
#pragma unroll
        for (int nt = 0; nt < 4; nt++) {
            int nu = ((wn * 64 + nt * 16) >> 3) + (lane >> 4);
            ldsm4t(br[nt], barea + kr * 256 + ((nu ^ (kr & 7)) * 16));
        }
#pragma unroll
        for (int nt = 0; nt < 4; nt++) {
            mma16816(acc[nt * 2 + 0], ar, br[nt][0], br[nt][1]);
            mma16816(acc[nt * 2 + 1], ar, br[nt][2], br[nt][3]);
        }
    }
    __syncthreads();   // smem reads done; safe to overwrite with prelu_s

    // ---- epilogue: bias + PReLU -> out2 + prelu_s ----
    float pw = __ldg(prelu_w);
    int o0 = wm * 16 + (lane >> 2);
    float b0v = bo_s[o0];
    float b1v = bo_s[o0 + 8];
#pragma unroll
    for (int nt = 0; nt < 4; nt++)
#pragma unroll
        for (int q = 0; q < 2; q++) {
            int ncol = wn * 64 + nt * 16 + q * 8 + (lane & 3) * 2;
            float* c4 = acc[nt * 2 + q];
            float v0 = c4[0] + b0v, v1 = c4[1] + b0v;
            float v2 = c4[2] + b1v, v3 = c4[3] + b1v;
            float p0 = v0 >= 0.f ? v0 : pw * v0;
            float p1 = v1 >= 0.f ? v1 : pw * v1;
            float p2 = v2 >= 0.f ? v2 : pw * v2;
            float p3 = v3 >= 0.f ? v3 : pw * v3;
            *(float2*)&out2[(size_t)(b * 128 + o0) * 1024 + n0 + ncol] =
                make_float2(p0, p1);
            *(float2*)&out2[(size_t)(b * 128 + o0 + 8) * 1024 + n0 + ncol] =
                make_float2(p2, p3);
            *(float2*)&prelu_s[o0 * 132 + ncol] = make_float2(p0, p1);
            *(float2*)&prelu_s[(o0 + 8) * 132 + ncol] = make_float2(p2, p3);
        }
    __syncthreads();

    // ---- readout conv: 256 threads, 2-way split over channels ----
    {
        int n = tid & 127;
        int half = tid >> 7;
        float r = 0.f;
        if (half == 0) {
            r = __ldg(b_read);
            for (int o = 0; o < 64; o++)
                r = fmaf(Wr_s[o], prelu_s[o * 132 + n], r);
        } else {
            for (int c = 0; c < 64; c++)
                r = fmaf(Wr_s[64 + c],
                         h[(size_t)(b * 64 + c) * 1024 + n0 + n], r);
        }
        rpart[half * 128 + n] = r;
    }
    __syncthreads();
    if (tid < 128)
        out[(size_t)b * 1024 + n0 + tid] = rpart[tid] + rpart[128 + tid];
}

// ---------------------------------------------------------------------------
extern "C" void kernel_launch(void* const* d_in, const int* in_sizes, int n_in,
                              void* d_out, int out_size)
{
    const float* x      = (const float*)d_in[0];
    const float* m      = (const float*)d_in[1];
    const float* u      = (const float*)d_in[2];
    const float* h      = (const float*)d_in[3];
    const float* adj    = (const float*)d_in[4];
    const float* W_in   = (const float*)d_in[5];
    const float* b_in   = (const float*)d_in[6];
    const float* W_gc   = (const float*)d_in[7];
    const float* b_gc   = (const float*)d_in[8];
    const float* W_out  = (const float*)d_in[9];
    const float* b_out  = (const float*)d_in[10];
    const float* W_read = (const float*)d_in[11];
    const float* b_read = (const float*)d_in[12];
    const float* prelu  = (const float*)d_in[13];
    float* out = (float*)d_out;

    cudaFuncSetAttribute(k_gemm_mma, cudaFuncAttributeMaxDynamicSharedMemorySize, GDYN);
    cudaFuncSetAttribute(k_out_mma, cudaFuncAttributeMaxDynamicSharedMemorySize, ODYN);

    k_adj<<<2048, 256>>>(adj);
    k_weff<<<35, 256>>>(W_in, b_in, W_gc);
    k_y<<<512, 128>>>(x, m, u, h);
    dim3 g(Nn / BN, (Bb * DMdim) / BM);   // (8, 64) = 512 CTAs
    k_gemm_mma<<<g, 128, GDYN>>>(b_gc);
    k_out_mma<<<1024, 256, ODYN>>>(h, W_out, b_out, W_read, b_read, prelu, out);
}

// round 15
// speedup vs baseline: 1.2998x; 1.0468x over previous
#include <cuda_runtime.h>
#include <cuda_bf16.h>

#define Bb 128
#define Nn 1024
#define DMdim 64
#define K2 2048   // S * Nn

// Scratch (no allocs): static device globals
__device__ __nv_bfloat16 g_yhi[(size_t)8192 * 2048];     // 32 MB
__device__ __nv_bfloat16 g_ahi[2 * 1024 * 1024];         // 4 MB
__device__ float g_weff[128 * 68];
__device__ float g_beff[128];

// ---------------------------------------------------------------------------
__device__ __forceinline__ unsigned s2u(const void* p) {
    unsigned a;
    asm("{ .reg .u64 t; cvta.to.shared.u64 t, %1; cvt.u32.u64 %0, t; }"
        : "=r"(a) : "l"(p));
    return a;
}
#define CP16(dst, src) \
    asm volatile("cp.async.cg.shared.global [%0], [%1], 16;" :: "r"(dst), "l"(src))
#define CP_COMMIT() asm volatile("cp.async.commit_group;" ::: "memory")
#define STS16(addr, v) \
    asm volatile("st.shared.u16 [%0], %1;" :: "r"(addr), "h"(v))
#define STS32(addr, v) \
    asm volatile("st.shared.u32 [%0], %1;" :: "r"(addr), "r"(v))
#define STS64(addr, v) \
    asm volatile("st.shared.b64 [%0], %1;" :: "r"(addr), "l"(v))

__device__ __forceinline__ unsigned short bf16u(float f) {
    __nv_bfloat16 t = __float2bfloat16(f);
    return *(unsigned short*)&t;
}
__device__ __forceinline__ unsigned long long packu2(unsigned a, unsigned b) {
    unsigned long long r;
    asm("mov.b64 %0, {%1, %2};" : "=l"(r) : "r"(a), "r"(b));
    return r;
}

// packed f32x2 helpers (FFMA2 path)
__device__ __forceinline__ unsigned long long pack2(float a, float b) {
    unsigned long long r;
    asm("mov.b64 %0, {%1, %2};" : "=l"(r) : "f"(a), "f"(b));
    return r;
}
__device__ __forceinline__ unsigned long long bcast2(float a) {
    unsigned long long r;
    asm("mov.b64 %0, {%1, %1};" : "=l"(r) : "f"(a));
    return r;
}
__device__ __forceinline__ void ffma2(unsigned long long& d,
                                      unsigned long long a, unsigned long long b) {
    asm("fma.rn.f32x2 %0, %1, %2, %0;" : "+l"(d) : "l"(a), "l"(b));
}
__device__ __forceinline__ float2 unpack2(unsigned long long v) {
    float x, y;
    asm("mov.b64 {%0, %1}, %2;" : "=f"(x), "=f"(y) : "l"(v));
    return make_float2(x, y);
}

__device__ __forceinline__ void ldsm4(unsigned* r, unsigned addr) {
    asm volatile("ldmatrix.sync.aligned.m8n8.x4.shared.b16 {%0,%1,%2,%3}, [%4];"
                 : "=r"(r[0]), "=r"(r[1]), "=r"(r[2]), "=r"(r[3]) : "r"(addr));
}
__device__ __forceinline__ void ldsm4t(unsigned* r, unsigned addr) {
    asm volatile("ldmatrix.sync.aligned.m8n8.x4.trans.shared.b16 {%0,%1,%2,%3}, [%4];"
                 : "=r"(r[0]), "=r"(r[1]), "=r"(r[2]), "=r"(r[3]) : "r"(addr));
}
__device__ __forceinline__ void mma16816(float* c, const unsigned* a,
                                         unsigned b0, unsigned b1) {
    asm volatile(
        "mma.sync.aligned.m16n8k16.row.col.f32.bf16.bf16.f32 "
        "{%0,%1,%2,%3}, {%4,%5,%6,%7}, {%8,%9}, {%0,%1,%2,%3};"
        : "+f"(c[0]), "+f"(c[1]), "+f"(c[2]), "+f"(c[3])
        : "r"(a[0]), "r"(a[1]), "r"(a[2]), "r"(a[3]), "r"(b0), "r"(b1));
}

// ---------------------------------------------------------------------------
// k_prep: adj->bf16 (blocks 0..2047) + W_eff fold (blocks 2048..2081)
//         + b_eff (block 2082)
// ---------------------------------------------------------------------------
__global__ __launch_bounds__(256) void k_prep(
    const float* __restrict__ adj, const float* __restrict__ W_in,
    const float* __restrict__ b_in, const float* __restrict__ W_gc)
{
    if (blockIdx.x < 2048) {
        int i = blockIdx.x * 256 + threadIdx.x;
        float4 v = ((const float4*)adj)[i];
        ((__nv_bfloat162*)g_ahi)[i * 2 + 0] = __halves2bfloat162(
            __float2bfloat16(v.x), __float2bfloat16(v.y));
        ((__nv_bfloat162*)g_ahi)[i * 2 + 1] = __halves2bfloat162(
            __float2bfloat16(v.z), __float2bfloat16(v.w));
    } else if (blockIdx.x < 2082) {
        int i = (blockIdx.x - 2048) * 256 + threadIdx.x;
        if (i < 128 * 68) {
            int op = i / 68, cp = i - op * 68;
            const float* wg = W_gc + (op & 63) * 128 + (op >> 6) * 64;
            float s = 0.f;
#pragma unroll 8
            for (int c = 0; c < 64; c++) s = fmaf(wg[c], W_in[c * 68 + cp], s);
            g_weff[op * 68 + cp] = s;
        }
    } else {
        if (threadIdx.x < 128) {
            int op = threadIdx.x;
            const float* wg = W_gc + (op & 63) * 128 + (op >> 6) * 64;
            float s = 0.f;
#pragma unroll 8
            for (int c = 0; c < 64; c++) s = fmaf(wg[c], b_in[c], s);
            g_beff[op] = s;
        }
    }
}

// ---------------------------------------------------------------------------
// k_y (R12-proven): FFMA2, 2 cols/thread, 4 chunks of 16 pairs.
// ---------------------------------------------------------------------------
__global__ __launch_bounds__(128) void k_y(
    const float* __restrict__ x, const float* __restrict__ m,
    const float* __restrict__ u, const float* __restrict__ h)
{
    __shared__ unsigned long long WPs[68][64];
    __shared__ unsigned long long bep[64];
    for (int i = threadIdx.x; i < 68 * 64; i += 128) {
        int cp = i >> 6, p = i & 63;
        WPs[cp][p] = pack2(g_weff[(2 * p) * 68 + cp], g_weff[(2 * p + 1) * 68 + cp]);
    }
    if (threadIdx.x < 64)
        bep[threadIdx.x] = pack2(g_beff[2 * threadIdx.x], g_beff[2 * threadIdx.x + 1]);
    __syncthreads();

    int b = blockIdx.x >> 2;
    int n0 = (blockIdx.x & 3) * 256 + threadIdx.x * 2;

    for (int ch = 0; ch < 4; ch++) {
        int p0 = ch * 16;
        unsigned long long acc[16][2];
#pragma unroll
        for (int i = 0; i < 16; i++) {
            unsigned long long bv = bep[p0 + i];
            acc[i][0] = bv; acc[i][1] = bv;
        }

#define YACC(cp, ptr) do {                                                     \
        float2 _v = *(const float2*)(ptr);                                     \
        unsigned long long _v0 = bcast2(_v.x), _v1 = bcast2(_v.y);             \
        _Pragma("unroll")                                                      \
        for (int i = 0; i < 16; i++) {                                         \
            unsigned long long _wp = WPs[cp][p0 + i];                          \
            ffma2(acc[i][0], _wp, _v0);                                        \
            ffma2(acc[i][1], _wp, _v1);                                        \
        }                                                                      \
    } while (0)

        YACC(0, &x[b * 1024 + n0]);
        YACC(1, &m[b * 1024 + n0]);
        YACC(2, &u[b * 2048 + n0]);
        YACC(3, &u[b * 2048 + 1024 + n0]);
        for (int c = 0; c < 64; c++)
            YACC(4 + c, &h[(b * 64 + c) * 1024 + n0]);
#undef YACC

#pragma unroll
        for (int i = 0; i < 16; i++) {
            float2 c0 = unpack2(acc[i][0]);
            float2 c1 = unpack2(acc[i][1]);
#pragma unroll
            for (int q = 0; q < 2; q++) {
                int op = ch * 32 + 2 * i + q;
                float v0 = q ? c0.y : c0.x;
                float v1 = q ? c1.y : c1.x;
                int s = op >> 6, oc = op & 63;
                size_t yi = (size_t)(b * 64 + oc) * K2 + s * 1024 + n0;
                __nv_bfloat162 hp = __halves2bfloat162(
                    __float2bfloat16(v0), __float2bfloat16(v1));
                *(unsigned*)&g_yhi[yi] = *(unsigned*)&hp;
            }
        }
    }
}

// ---------------------------------------------------------------------------
// k_gemm_fused: proven gemm mainloop + fully fused k_out epilogue.
// Grid (8, 64) = 512 CTAs, 128 thr, GDYN = 96 KB, 2 CTAs/SM.
// Post-mainloop smem layout: W_out A 32KB @0 | gc(b0) 16KB @32768 |
//   gc(b1) 16KB @49152 | h 32KB @65536 (reused per b; prelu_s overlays it).
// ---------------------------------------------------------------------------
#define BM 128
#define BN 128
#define BK 64
#define ASTG (128 * 128)
#define STGB (2 * ASTG)
#define GDYN (3 * STGB)
#define NCHK 32

__device__ __forceinline__ void load_chunk(unsigned base, int st, int t,
                                           int bm, int bn, int tid)
{
    int k0 = t * BK;
    int s = k0 >> 10;
    int v0 = k0 & 1023;
    unsigned ab = base + st * STGB;
    unsigned bb = ab + ASTG;
#pragma unroll
    for (int i = 0; i < 8; i++) {
        int u2 = tid + i * 128;
        int row = u2 >> 3, j = u2 & 7;
        CP16(ab + row * 128 + ((j ^ (row & 7)) * 16),
             (const char*)(g_yhi + (size_t)(bm + row) * K2 + k0 + j * 8));
    }
#pragma unroll
    for (int i = 0; i < 8; i++) {
        int u2 = tid + i * 128;
        int row = u2 >> 3, j = u2 & 7;
        CP16(bb + row * 128 + ((j ^ (row & 7)) * 16),
             (const char*)(g_ahi + (size_t)s * 1048576 +
                           (size_t)(bn + row) * 1024 + v0 + j * 8));
    }
    CP_COMMIT();
}

__global__ __launch_bounds__(128, 2) void k_gemm_fused(
    const float* __restrict__ b_gc, const float* __restrict__ h,
    const float* __restrict__ W_out, const float* __restrict__ b_out,
    const float* __restrict__ W_read, const float* __restrict__ b_read,
    const float* __restrict__ prelu_w, float* __restrict__ out)
{
    extern __shared__ __align__(16) char dsm[];
    unsigned base = s2u(dsm);

    __shared__ float Wr_s[128];
    __shared__ float bo_s[64];

    int tid = threadIdx.x;
    int lane = tid & 31;
    int wid = tid >> 5;
    int wm = wid >> 1;
    int wn = wid & 1;
    int bm = blockIdx.y * BM;
    int bn = blockIdx.x * BN;
    int n0 = bn;
    int b0 = blockIdx.y * 2;
    float* out2 = out + (size_t)Bb * Nn;

    Wr_s[tid] = W_read[tid];
    if (tid < 64) bo_s[tid] = b_out[tid];

    // ================= mainloop (proven) =================
    float acc[4][8][4];
#pragma unroll
    for (int i = 0; i < 4; i++)
#pragma unroll
        for (int j = 0; j < 8; j++)
#pragma unroll
            for (int q = 0; q < 4; q++) acc[i][j][q] = 0.f;

    load_chunk(base, 0, 0, bm, bn, tid);
    load_chunk(base, 1, 1, bm, bn, tid);

    int st = 0;
    for (int t = 0; t < NCHK; t++) {
        if (t == NCHK - 1) asm volatile("cp.async.wait_group 0;" ::: "memory");
        else               asm volatile("cp.async.wait_group 1;" ::: "memory");
        __syncthreads();

        if (t + 2 < NCHK) {
            int st2 = st + 2; if (st2 >= 3) st2 -= 3;
            load_chunk(base, st2, t + 2, bm, bn, tid);
        }

        unsigned abuf = base + st * STGB;
        unsigned bbuf = abuf + ASTG;

#pragma unroll
        for (int kk = 0; kk < 4; kk++) {
            unsigned ar[4][4];
#pragma unroll
            for (int mf = 0; mf < 4; mf++) {
                int mrow = wm * 64 + mf * 16 + (lane & 7) + ((lane >> 3) & 1) * 8;
                int uidx = kk * 2 + (lane >> 4);
                ldsm4(ar[mf], abuf + mrow * 128 + ((uidx ^ (mrow & 7)) * 16));
            }
            unsigned br[4][4];
#pragma unroll
            for (int nt = 0; nt < 4; nt++) {
                int nrow = wn * 64 + nt * 16 + (lane & 7) + (lane >> 4) * 8;
                int uidx = kk * 2 + ((lane >> 3) & 1);
                ldsm4(br[nt], bbuf + nrow * 128 + ((uidx ^ (nrow & 7)) * 16));
            }
#pragma unroll
            for (int mf = 0; mf < 4; mf++)
#pragma unroll
                for (int nt = 0; nt < 4; nt++) {
                    mma16816(acc[mf][nt * 2 + 0], ar[mf], br[nt][0], br[nt][1]);
                    mma16816(acc[mf][nt * 2 + 1], ar[mf], br[nt][2], br[nt][3]);
                }
        }
        st++; if (st >= 3) st = 0;
    }
    __syncthreads();   // all warps done reading stages; smem is ours

    // ================= fused k_out epilogue =================
    unsigned As = base;             // W_out [o64][k192] rows 512B
    unsigned gcA0 = base + 32768;   // gc(b0) [o64][n128] rows 256B
    unsigned gcA1 = base + 49152;   // gc(b1)
    unsigned hAa = base + 65536;    // h [k128][n128] rows 256B (reused)
    float* prelu_s = (float*)(dsm + 65536);   // stride 128 floats = 32KB exact

    // stage W_out (2048 float4 over 128 thr)
#pragma unroll
    for (int i = 0; i < 16; i++) {
        int u = tid + i * 128;
        int o = u >> 5, f4 = u & 31;
        float4 w = *(const float4*)&W_out[o * 128 + f4 * 4];
        float vv[4] = {w.x, w.y, w.z, w.w};
        unsigned rowa = As + o * 512;
        unsigned x7 = (o & 7);
#pragma unroll
        for (int j = 0; j < 4; j++) {
            int c = f4 * 4 + j;
            if (c < 64) {
                STS16(rowa + (((c >> 3) ^ x7) * 16) + (c & 7) * 2, bf16u(vv[j]));
            } else {
                __nv_bfloat16 hb = __float2bfloat16(vv[j]);
                unsigned short hu = *(unsigned short*)&hb;
                unsigned short lu = bf16u(vv[j] - __bfloat162float(hb));
                int k1 = c;
                int k2 = c + 64;
                STS16(rowa + (((k1 >> 3) ^ x7) * 16) + (k1 & 7) * 2, hu);
                STS16(rowa + (((k2 >> 3) ^ x7) * 16) + (k2 & 7) * 2, lu);
            }
        }
    }

    // stage gc(b0) and gc(b1) from live accumulators (bias + bf16 round)
#pragma unroll
    for (int mf = 0; mf < 4; mf++) {
        int r0 = wm * 64 + mf * 16 + (lane >> 2);
#pragma unroll
        for (int nf = 0; nf < 8; nf++) {
            int col = wn * 64 + nf * 8 + (lane & 3) * 2;
            float* c4 = acc[mf][nf];
#pragma unroll
            for (int rr = 0; rr < 2; rr++) {
                int row = r0 + rr * 8;             // 0..127 within tile
                int o = row & 63;
                float bias = __ldg(&b_gc[o]);
                __nv_bfloat162 pv = __halves2bfloat162(
                    __float2bfloat16(c4[rr * 2 + 0] + bias),
                    __float2bfloat16(c4[rr * 2 + 1] + bias));
                unsigned area = (row >> 6) ? gcA1 : gcA0;
                STS32(area + o * 256 + (((col >> 3) ^ (o & 7)) * 16) + (col & 7) * 2,
                      *(unsigned*)&pv);
            }
        }
    }

    for (int bi = 0; bi < 2; bi++) {
        int b = b0 + bi;
        unsigned gcA = bi ? gcA1 : gcA0;

        // ---- stage h (hi/lo) + fused exact h copy to out2 ----
#pragma unroll
        for (int i = 0; i < 16; i++) {
            int u = tid + i * 128;
            int c = u >> 5, n = (u & 31) * 4;
            float4 hv = *(const float4*)&h[(size_t)(b * 64 + c) * 1024 + n0 + n];
            *(float4*)&out2[(size_t)(b * 128 + 64 + c) * 1024 + n0 + n] = hv;
            __nv_bfloat16 h0 = __float2bfloat16(hv.x);
            __nv_bfloat16 h1 = __float2bfloat16(hv.y);
            __nv_bfloat16 h2 = __float2bfloat16(hv.z);
            __nv_bfloat16 h3 = __float2bfloat16(hv.w);
            __nv_bfloat162 hp0 = __halves2bfloat162(h0, h1);
            __nv_bfloat162 hp1 = __halves2bfloat162(h2, h3);
            unsigned long long hip = packu2(*(unsigned*)&hp0, *(unsigned*)&hp1);
            __nv_bfloat162 lp0 = __halves2bfloat162(
                __float2bfloat16(hv.x - __bfloat162float(h0)),
                __float2bfloat16(hv.y - __bfloat162float(h1)));
            __nv_bfloat162 lp1 = __halves2bfloat162(
                __float2bfloat16(hv.z - __bfloat162float(h2)),
                __float2bfloat16(hv.w - __bfloat162float(h3)));
            unsigned long long lop = packu2(*(unsigned*)&lp0, *(unsigned*)&lp1);
            unsigned sw = (((n >> 3) ^ (c & 7)) * 16) + (n & 7) * 2;
            STS64(hAa + c * 256 + sw, hip);
            STS64(hAa + (c + 64) * 256 + sw, lop);
        }
        __syncthreads();

        // ---- mma: M=64 N=128 K=256; 4 warps, warp tile m16 x n128 ----
        float accO[8][2][4];
#pragma unroll
        for (int j = 0; j < 8; j++)
#pragma unroll
            for (int q = 0; q < 2; q++)
#pragma unroll
                for (int z = 0; z < 4; z++) accO[j][q][z] = 0.f;

#pragma unroll
        for (int kk = 0; kk < 16; kk++) {
            int akk = (kk < 8) ? kk : kk - 4;
            unsigned ar[4];
            int mrow = wid * 16 + (lane & 7) + ((lane >> 3) & 1) * 8;
            int uA = akk * 2 + (lane >> 4);
            ldsm4(ar, As + mrow * 512 + ((uA ^ (mrow & 7)) * 16));

            unsigned barea; int kbase;
            if (kk < 4)       { barea = gcA; kbase = kk * 16; }
            else if (kk < 8)  { barea = hAa; kbase = (kk - 4) * 16; }
            else if (kk < 12) { barea = hAa; kbase = 64 + (kk - 8) * 16; }
            else              { barea = hAa; kbase = (kk - 12) * 16; }
            int kr = kbase + (lane & 7) + ((lane >> 3) & 1) * 8;

#pragma unroll
            for (int nt = 0; nt < 8; nt++) {
                unsigned br[4];
                int nu = nt * 2 + (lane >> 4);
                ldsm4t(br, barea + kr * 256 + ((nu ^ (kr & 7)) * 16));
                mma16816(accO[nt][0], ar, br[0], br[1]);
                mma16816(accO[nt][1], ar, br[2], br[3]);
            }
        }
        __syncthreads();   // mma smem reads done; prelu_s may overwrite h area

        // ---- epilogue: bias + PReLU -> out2 + prelu_s ----
        float pw = __ldg(prelu_w);
        int o0 = wid * 16 + (lane >> 2);
        float b0v = bo_s[o0];
        float b1v = bo_s[o0 + 8];
#pragma unroll
        for (int nt = 0; nt < 8; nt++)
#pragma unroll
            for (int q = 0; q < 2; q++) {
                int ncol = nt * 16 + q * 8 + (lane & 3) * 2;
                float* c4 = accO[nt][q];
                float v0 = c4[0] + b0v, v1 = c4[1] + b0v;
                float v2 = c4[2] + b1v, v3 = c4[3] + b1v;
                float p0 = v0 >= 0.f ? v0 : pw * v0;
                float p1 = v1 >= 0.f ? v1 : pw * v1;
                float p2 = v2 >= 0.f ? v2 : pw * v2;
                float p3 = v3 >= 0.f ? v3 : pw * v3;
                *(float2*)&out2[(size_t)(b * 128 + o0) * 1024 + n0 + ncol] =
                    make_float2(p0, p1);
                *(float2*)&out2[(size_t)(b * 128 + o0 + 8) * 1024 + n0 + ncol] =
                    make_float2(p2, p3);
                *(float2*)&prelu_s[o0 * 128 + ncol] = make_float2(p0, p1);
                *(float2*)&prelu_s[(o0 + 8) * 128 + ncol] = make_float2(p2, p3);
            }
        __syncthreads();

        // ---- readout: 128 threads, one n each ----
        {
            float r = __ldg(b_read);
            for (int o = 0; o < 64; o++)
                r = fmaf(Wr_s[o], prelu_s[o * 128 + tid], r);
            for (int c = 0; c < 64; c++)
                r = fmaf(Wr_s[64 + c],
                         h[(size_t)(b * 64 + c) * 1024 + n0 + tid], r);
            out[(size_t)b * 1024 + n0 + tid] = r;
        }
        __syncthreads();   // readout done before next bi overwrites prelu/h
    }
}

// ---------------------------------------------------------------------------
extern "C" void kernel_launch(void* const* d_in, const int* in_sizes, int n_in,
                              void* d_out, int out_size)
{
    const float* x      = (const float*)d_in[0];
    const float* m      = (const float*)d_in[1];
    const float* u      = (const float*)d_in[2];
    const float* h      = (const float*)d_in[3];
    const float* adj    = (const float*)d_in[4];
    const float* W_in   = (const float*)d_in[5];
    const float* b_in   = (const float*)d_in[6];
    const float* W_gc   = (const float*)d_in[7];
    const float* b_gc   = (const float*)d_in[8];
    const float* W_out  = (const float*)d_in[9];
    const float* b_out  = (const float*)d_in[10];
    const float* W_read = (const float*)d_in[11];
    const float* b_read = (const float*)d_in[12];
    const float* prelu  = (const float*)d_in[13];
    float* out = (float*)d_out;

    cudaFuncSetAttribute(k_gemm_fused, cudaFuncAttributeMaxDynamicSharedMemorySize, GDYN);

    k_prep<<<2083, 256>>>(adj, W_in, b_in, W_gc);
    k_y<<<512, 128>>>(x, m, u, h);
    dim3 g(Nn / BN, (Bb * DMdim) / BM);   // (8, 64) = 512 CTAs
    k_gemm_fused<<<g, 128, GDYN>>>(b_gc, h, W_out, b_out, W_read, b_read, prelu, out);
}

// round 16
// speedup vs baseline: 1.5538x; 1.1954x over previous
#include <cuda_runtime.h>
#include <cuda_bf16.h>

#define Bb 128
#define Nn 1024
#define DMdim 64
#define K2 2048   // S * Nn

// Scratch (no allocs): static device globals
__device__ __nv_bfloat16 g_yhi[(size_t)8192 * 2048];     // 32 MB
__device__ __nv_bfloat16 g_ahi[2 * 1024 * 1024];         // 4 MB
__device__ float g_weff[128 * 68];
__device__ float g_beff[128];

// ---------------------------------------------------------------------------
__device__ __forceinline__ unsigned s2u(const void* p) {
    unsigned a;
    asm("{ .reg .u64 t; cvta.to.shared.u64 t, %1; cvt.u32.u64 %0, t; }"
        : "=r"(a) : "l"(p));
    return a;
}
#define CP16(dst, src) \
    asm volatile("cp.async.cg.shared.global [%0], [%1], 16;" :: "r"(dst), "l"(src))
#define CP_COMMIT() asm volatile("cp.async.commit_group;" ::: "memory")
#define STS16(addr, v) \
    asm volatile("st.shared.u16 [%0], %1;" :: "r"(addr), "h"(v))
#define STS32(addr, v) \
    asm volatile("st.shared.u32 [%0], %1;" :: "r"(addr), "r"(v))
#define STS64(addr, v) \
    asm volatile("st.shared.b64 [%0], %1;" :: "r"(addr), "l"(v))

__device__ __forceinline__ unsigned short bf16u(float f) {
    __nv_bfloat16 t = __float2bfloat16(f);
    return *(unsigned short*)&t;
}
__device__ __forceinline__ unsigned long long packu2(unsigned a, unsigned b) {
    unsigned long long r;
    asm("mov.b64 %0, {%1, %2};" : "=l"(r) : "r"(a), "r"(b));
    return r;
}

__device__ __forceinline__ void ldsm4(unsigned* r, unsigned addr) {
    asm volatile("ldmatrix.sync.aligned.m8n8.x4.shared.b16 {%0,%1,%2,%3}, [%4];"
                 : "=r"(r[0]), "=r"(r[1]), "=r"(r[2]), "=r"(r[3]) : "r"(addr));
}
__device__ __forceinline__ void ldsm4t(unsigned* r, unsigned addr) {
    asm volatile("ldmatrix.sync.aligned.m8n8.x4.trans.shared.b16 {%0,%1,%2,%3}, [%4];"
                 : "=r"(r[0]), "=r"(r[1]), "=r"(r[2]), "=r"(r[3]) : "r"(addr));
}
__device__ __forceinline__ void mma16816(float* c, const unsigned* a,
                                         unsigned b0, unsigned b1) {
    asm volatile(
        "mma.sync.aligned.m16n8k16.row.col.f32.bf16.bf16.f32 "
        "{%0,%1,%2,%3}, {%4,%5,%6,%7}, {%8,%9}, {%0,%1,%2,%3};"
        : "+f"(c[0]), "+f"(c[1]), "+f"(c[2]), "+f"(c[3])
        : "r"(a[0]), "r"(a[1]), "r"(a[2]), "r"(a[3]), "r"(b0), "r"(b1));
}

// ---------------------------------------------------------------------------
// k_prep: adj->bf16 (blocks 0..2047) + W_eff fold (blocks 2048..2081)
//         + b_eff (block 2082)
// ---------------------------------------------------------------------------
__global__ __launch_bounds__(256) void k_prep(
    const float* __restrict__ adj, const float* __restrict__ W_in,
    const float* __restrict__ b_in, const float* __restrict__ W_gc)
{
    if (blockIdx.x < 2048) {
        int i = blockIdx.x * 256 + threadIdx.x;
        float4 v = ((const float4*)adj)[i];
        ((__nv_bfloat162*)g_ahi)[i * 2 + 0] = __halves2bfloat162(
            __float2bfloat16(v.x), __float2bfloat16(v.y));
        ((__nv_bfloat162*)g_ahi)[i * 2 + 1] = __halves2bfloat162(
            __float2bfloat16(v.z), __float2bfloat16(v.w));
    } else if (blockIdx.x < 2082) {
        int i = (blockIdx.x - 2048) * 256 + threadIdx.x;
        if (i < 128 * 68) {
            int op = i / 68, cp = i - op * 68;
            const float* wg = W_gc + (op & 63) * 128 + (op >> 6) * 64;
            float s = 0.f;
#pragma unroll 8
            for (int c = 0; c < 64; c++) s = fmaf(wg[c], W_in[c * 68 + cp], s);
            g_weff[op * 68 + cp] = s;
        }
    } else {
        if (threadIdx.x < 128) {
            int op = threadIdx.x;
            const float* wg = W_gc + (op & 63) * 128 + (op >> 6) * 64;
            float s = 0.f;
#pragma unroll 8
            for (int c = 0; c < 64; c++) s = fmaf(wg[c], b_in[c], s);
            g_beff[op] = s;
        }
    }
}

// ---------------------------------------------------------------------------
// k_y_mma: tensor-core y.  y[128 out][128 n] = W_eff(bf16) @ X(bf16) + b_eff
// per CTA; grid = 128 b x 8 n-blocks = 1024 CTAs, 128 thr (4 warps).
// A [m=128][k=128pad] rows 256B; B [k=128pad][n=128] rows 256B (trans-ldsm).
// B rows: 0=x 1=m 2=u0 3=u1, 4..67=h, 68..127=0.
// ---------------------------------------------------------------------------
#define YDYN 65536

__global__ __launch_bounds__(128, 2) void k_y_mma(
    const float* __restrict__ x, const float* __restrict__ m,
    const float* __restrict__ u, const float* __restrict__ h)
{
    extern __shared__ __align__(16) char dsm[];
    unsigned As = s2u(dsm);
    unsigned Bs = As + 32768;
    __shared__ float be_s[128];

    int tid = threadIdx.x;
    int lane = tid & 31;
    int wid = tid >> 5;
    int b = blockIdx.x >> 3;
    int n0 = (blockIdx.x & 7) * 128;

    be_s[tid] = g_beff[tid];

    // zero all 64KB (pad regions must be 0; rest overwritten)
#pragma unroll
    for (int i = 0; i < 32; i++)
        ((float4*)dsm)[tid + i * 128] = make_float4(0.f, 0.f, 0.f, 0.f);
    __syncthreads();

    // stage A: W_eff [op][cp] -> bf16 swizzled
    for (int i = 0; i < 68; i++) {
        int idx = tid + i * 128;
        if (idx < 128 * 68) {
            int op = idx / 68, cp = idx - op * 68;
            float w = g_weff[idx];
            STS16(As + op * 256 + (((cp >> 3) ^ (op & 7)) * 16) + (cp & 7) * 2,
                  bf16u(w));
        }
    }

    // stage B rows 0..3 (x, m, u0, u1)
    {
        int r = tid >> 5;
        int nq = (tid & 31) * 4;
        const float* src;
        if (r == 0) src = x + b * 1024;
        else if (r == 1) src = m + b * 1024;
        else if (r == 2) src = u + b * 2048;
        else src = u + b * 2048 + 1024;
        float4 v = *(const float4*)&src[n0 + nq];
        __nv_bfloat162 p0 = __halves2bfloat162(
            __float2bfloat16(v.x), __float2bfloat16(v.y));
        __nv_bfloat162 p1 = __halves2bfloat162(
            __float2bfloat16(v.z), __float2bfloat16(v.w));
        unsigned sw = (((nq >> 3) ^ (r & 7)) * 16) + (nq & 7) * 2;
        STS64(Bs + r * 256 + sw, packu2(*(unsigned*)&p0, *(unsigned*)&p1));
    }
    // stage B rows 4..67 (h)
#pragma unroll
    for (int i = 0; i < 16; i++) {
        int uidx = tid + i * 128;
        int c = uidx >> 5, nq = (uidx & 31) * 4;
        float4 v = *(const float4*)&h[(size_t)(b * 64 + c) * 1024 + n0 + nq];
        __nv_bfloat162 p0 = __halves2bfloat162(
            __float2bfloat16(v.x), __float2bfloat16(v.y));
        __nv_bfloat162 p1 = __halves2bfloat162(
            __float2bfloat16(v.z), __float2bfloat16(v.w));
        int r = 4 + c;
        unsigned sw = (((nq >> 3) ^ (r & 7)) * 16) + (nq & 7) * 2;
        STS64(Bs + r * 256 + sw, packu2(*(unsigned*)&p0, *(unsigned*)&p1));
    }
    __syncthreads();

    // mma: warp m32 x n128, 8 k16-steps
    float acc[2][8][2][4];
#pragma unroll
    for (int a = 0; a < 2; a++)
#pragma unroll
        for (int nt = 0; nt < 8; nt++)
#pragma unroll
            for (int q = 0; q < 2; q++)
#pragma unroll
                for (int z = 0; z < 4; z++) acc[a][nt][q][z] = 0.f;

#pragma unroll
    for (int kk = 0; kk < 8; kk++) {
        unsigned ar[2][4];
#pragma unroll
        for (int mf = 0; mf < 2; mf++) {
            int mrow = wid * 32 + mf * 16 + (lane & 7) + ((lane >> 3) & 1) * 8;
            int uA = kk * 2 + (lane >> 4);
            ldsm4(ar[mf], As + mrow * 256 + ((uA ^ (mrow & 7)) * 16));
        }
        int kr = kk * 16 + (lane & 7) + ((lane >> 3) & 1) * 8;
#pragma unroll
        for (int nt = 0; nt < 8; nt++) {
            unsigned br[4];
            int nu = nt * 2 + (lane >> 4);
            ldsm4t(br, Bs + kr * 256 + ((nu ^ (kr & 7)) * 16));
#pragma unroll
            for (int mf = 0; mf < 2; mf++) {
                mma16816(acc[mf][nt][0], ar[mf], br[0], br[1]);
                mma16816(acc[mf][nt][1], ar[mf], br[2], br[3]);
            }
        }
    }

    // epilogue: + b_eff, round bf16, store y
#pragma unroll
    for (int mf = 0; mf < 2; mf++) {
        int r0 = wid * 32 + mf * 16 + (lane >> 2);
#pragma unroll
        for (int rr = 0; rr < 2; rr++) {
            int op = r0 + rr * 8;
            float bias = be_s[op];
            int s = op >> 6, oc = op & 63;
            size_t ybase = (size_t)(b * 64 + oc) * K2 + s * 1024 + n0;
#pragma unroll
            for (int nt = 0; nt < 8; nt++)
#pragma unroll
                for (int q = 0; q < 2; q++) {
                    int col = nt * 16 + q * 8 + (lane & 3) * 2;
                    float* c4 = acc[mf][nt][q];
                    __nv_bfloat162 pv = __halves2bfloat162(
                        __float2bfloat16(c4[rr * 2 + 0] + bias),
                        __float2bfloat16(c4[rr * 2 + 1] + bias));
                    *(unsigned*)&g_yhi[ybase + col] = *(unsigned*)&pv;
                }
        }
    }
}

// ---------------------------------------------------------------------------
// k_gemm_fused (unchanged from R15 — proven): gemm mainloop + fused k_out.
// ---------------------------------------------------------------------------
#define BM 128
#define BN 128
#define BK 64
#define ASTG (128 * 128)
#define STGB (2 * ASTG)
#define GDYN (3 * STGB)
#define NCHK 32

__device__ __forceinline__ void load_chunk(unsigned base, int st, int t,
                                           int bm, int bn, int tid)
{
    int k0 = t * BK;
    int s = k0 >> 10;
    int v0 = k0 & 1023;
    unsigned ab = base + st * STGB;
    unsigned bb = ab + ASTG;
#pragma unroll
    for (int i = 0; i < 8; i++) {
        int u2 = tid + i * 128;
        int row = u2 >> 3, j = u2 & 7;
        CP16(ab + row * 128 + ((j ^ (row & 7)) * 16),
             (const char*)(g_yhi + (size_t)(bm + row) * K2 + k0 + j * 8));
    }
#pragma unroll
    for (int i = 0; i < 8; i++) {
        int u2 = tid + i * 128;
        int row = u2 >> 3, j = u2 & 7;
        CP16(bb + row * 128 + ((j ^ (row & 7)) * 16),
             (const char*)(g_ahi + (size_t)s * 1048576 +
                           (size_t)(bn + row) * 1024 + v0 + j * 8));
    }
    CP_COMMIT();
}

__global__ __launch_bounds__(128, 2) void k_gemm_fused(
    const float* __restrict__ b_gc, const float* __restrict__ h,
    const float* __restrict__ W_out, const float* __restrict__ b_out,
    const float* __restrict__ W_read, const float* __restrict__ b_read,
    const float* __restrict__ prelu_w, float* __restrict__ out)
{
    extern __shared__ __align__(16) char dsm[];
    unsigned base = s2u(dsm);

    __shared__ float Wr_s[128];
    __shared__ float bo_s[64];

    int tid = threadIdx.x;
    int lane = tid & 31;
    int wid = tid >> 5;
    int wm = wid >> 1;
    int wn = wid & 1;
    int bm = blockIdx.y * BM;
    int bn = blockIdx.x * BN;
    int n0 = bn;
    int b0 = blockIdx.y * 2;
    float* out2 = out + (size_t)Bb * Nn;

    Wr_s[tid] = W_read[tid];
    if (tid < 64) bo_s[tid] = b_out[tid];

    // ================= mainloop =================
    float acc[4][8][4];
#pragma unroll
    for (int i = 0; i < 4; i++)
#pragma unroll
        for (int j = 0; j < 8; j++)
#pragma unroll
            for (int q = 0; q < 4; q++) acc[i][j][q] = 0.f;

    load_chunk(base, 0, 0, bm, bn, tid);
    load_chunk(base, 1, 1, bm, bn, tid);

    int st = 0;
    for (int t = 0; t < NCHK; t++) {
        if (t == NCHK - 1) asm volatile("cp.async.wait_group 0;" ::: "memory");
        else               asm volatile("cp.async.wait_group 1;" ::: "memory");
        __syncthreads();

        if (t + 2 < NCHK) {
            int st2 = st + 2; if (st2 >= 3) st2 -= 3;
            load_chunk(base, st2, t + 2, bm, bn, tid);
        }

        unsigned abuf = base + st * STGB;
        unsigned bbuf = abuf + ASTG;

#pragma unroll
        for (int kk = 0; kk < 4; kk++) {
            unsigned ar[4][4];
#pragma unroll
            for (int mf = 0; mf < 4; mf++) {
                int mrow = wm * 64 + mf * 16 + (lane & 7) + ((lane >> 3) & 1) * 8;
                int uidx = kk * 2 + (lane >> 4);
                ldsm4(ar[mf], abuf + mrow * 128 + ((uidx ^ (mrow & 7)) * 16));
            }
            unsigned br[4][4];
#pragma unroll
            for (int nt = 0; nt < 4; nt++) {
                int nrow = wn * 64 + nt * 16 + (lane & 7) + (lane >> 4) * 8;
                int uidx = kk * 2 + ((lane >> 3) & 1);
                ldsm4(br[nt], bbuf + nrow * 128 + ((uidx ^ (nrow & 7)) * 16));
            }
#pragma unroll
            for (int mf = 0; mf < 4; mf++)
#pragma unroll
                for (int nt = 0; nt < 4; nt++) {
                    mma16816(acc[mf][nt * 2 + 0], ar[mf], br[nt][0], br[nt][1]);
                    mma16816(acc[mf][nt * 2 + 1], ar[mf], br[nt][2], br[nt][3]);
                }
        }
        st++; if (st >= 3) st = 0;
    }
    __syncthreads();

    // ================= fused k_out epilogue =================
    unsigned As = base;
    unsigned gcA0 = base + 32768;
    unsigned gcA1 = base + 49152;
    unsigned hAa = base + 65536;
    float* prelu_s = (float*)(dsm + 65536);

#pragma unroll
    for (int i = 0; i < 16; i++) {
        int u = tid + i * 128;
        int o = u >> 5, f4 = u & 31;
        float4 w = *(const float4*)&W_out[o * 128 + f4 * 4];
        float vv[4] = {w.x, w.y, w.z, w.w};
        unsigned rowa = As + o * 512;
        unsigned x7 = (o & 7);
#pragma unroll
        for (int j = 0; j < 4; j++) {
            int c = f4 * 4 + j;
            if (c < 64) {
                STS16(rowa + (((c >> 3) ^ x7) * 16) + (c & 7) * 2, bf16u(vv[j]));
            } else {
                __nv_bfloat16 hb = __float2bfloat16(vv[j]);
                unsigned short hu = *(unsigned short*)&hb;
                unsigned short lu = bf16u(vv[j] - __bfloat162float(hb));
                int k1 = c;
                int k2 = c + 64;
                STS16(rowa + (((k1 >> 3) ^ x7) * 16) + (k1 & 7) * 2, hu);
                STS16(rowa + (((k2 >> 3) ^ x7) * 16) + (k2 & 7) * 2, lu);
            }
        }
    }

#pragma unroll
    for (int mf = 0; mf < 4; mf++) {
        int r0 = wm * 64 + mf * 16 + (lane >> 2);
#pragma unroll
        for (int nf = 0; nf < 8; nf++) {
            int col = wn * 64 + nf * 8 + (lane & 3) * 2;
            float* c4 = acc[mf][nf];
#pragma unroll
            for (int rr = 0; rr < 2; rr++) {
                int row = r0 + rr * 8;
                int o = row & 63;
                float bias = __ldg(&b_gc[o]);
                __nv_bfloat162 pv = __halves2bfloat162(
                    __float2bfloat16(c4[rr * 2 + 0] + bias),
                    __float2bfloat16(c4[rr * 2 + 1] + bias));
                unsigned area = (row >> 6) ? gcA1 : gcA0;
                STS32(area + o * 256 + (((col >> 3) ^ (o & 7)) * 16) + (col & 7) * 2,
                      *(unsigned*)&pv);
            }
        }
    }

    for (int bi = 0; bi < 2; bi++) {
        int b = b0 + bi;
        unsigned gcA = bi ? gcA1 : gcA0;

#pragma unroll
        for (int i = 0; i < 16; i++) {
            int u = tid + i * 128;
            int c = u >> 5, n = (u & 31) * 4;
            float4 hv = *(const float4*)&h[(size_t)(b * 64 + c) * 1024 + n0 + n];
            *(float4*)&out2[(size_t)(b * 128 + 64 + c) * 1024 + n0 + n] = hv;
            __nv_bfloat16 h0 = __float2bfloat16(hv.x);
            __nv_bfloat16 h1 = __float2bfloat16(hv.y);
            __nv_bfloat16 h2 = __float2bfloat16(hv.z);
            __nv_bfloat16 h3 = __float2bfloat16(hv.w);
            __nv_bfloat162 hp0 = __halves2bfloat162(h0, h1);
            __nv_bfloat162 hp1 = __halves2bfloat162(h2, h3);
            unsigned long long hip = packu2(*(unsigned*)&hp0, *(unsigned*)&hp1);
            __nv_bfloat162 lp0 = __halves2bfloat162(
                __float2bfloat16(hv.x - __bfloat162float(h0)),
                __float2bfloat16(hv.y - __bfloat162float(h1)));
            __nv_bfloat162 lp1 = __halves2bfloat162(
                __float2bfloat16(hv.z - __bfloat162float(h2)),
                __float2bfloat16(hv.w - __bfloat162float(h3)));
            unsigned long long lop = packu2(*(unsigned*)&lp0, *(unsigned*)&lp1);
            unsigned sw = (((n >> 3) ^ (c & 7)) * 16) + (n & 7) * 2;
            STS64(hAa + c * 256 + sw, hip);
            STS64(hAa + (c + 64) * 256 + sw, lop);
        }
        __syncthreads();

        float accO[8][2][4];
#pragma unroll
        for (int j = 0; j < 8; j++)
#pragma unroll
            for (int q = 0; q < 2; q++)
#pragma unroll
                for (int z = 0; z < 4; z++) accO[j][q][z] = 0.f;

#pragma unroll
        for (int kk = 0; kk < 16; kk++) {
            int akk = (kk < 8) ? kk : kk - 4;
            unsigned ar[4];
            int mrow = wid * 16 + (lane & 7) + ((lane >> 3) & 1) * 8;
            int uA = akk * 2 + (lane >> 4);
            ldsm4(ar, As + mrow * 512 + ((uA ^ (mrow & 7)) * 16));

            unsigned barea; int kbase;
            if (kk < 4)       { barea = gcA; kbase = kk * 16; }
            else if (kk < 8)  { barea = hAa; kbase = (kk - 4) * 16; }
            else if (kk < 12) { barea = hAa; kbase = 64 + (kk - 8) * 16; }
            else              { barea = hAa; kbase = (kk - 12) * 16; }
            int kr = kbase + (lane & 7) + ((lane >> 3) & 1) * 8;

#pragma unroll
            for (int nt = 0; nt < 8; nt++) {
                unsigned br[4];
                int nu = nt * 2 + (lane >> 4);
                ldsm4t(br, barea + kr * 256 + ((nu ^ (kr & 7)) * 16));
                mma16816(accO[nt][0], ar, br[0], br[1]);
                mma16816(accO[nt][1], ar, br[2], br[3]);
            }
        }
        __syncthreads();

        float pw = __ldg(prelu_w);
        int o0 = wid * 16 + (lane >> 2);
        float b0v = bo_s[o0];
        float b1v = bo_s[o0 + 8];
#pragma unroll
        for (int nt = 0; nt < 8; nt++)
#pragma unroll
            for (int q = 0; q < 2; q++) {
                int ncol = nt * 16 + q * 8 + (lane & 3) * 2;
                float* c4 = accO[nt][q];
                float v0 = c4[0] + b0v, v1 = c4[1] + b0v;
                float v2 = c4[2] + b1v, v3 = c4[3] + b1v;
                float p0 = v0 >= 0.f ? v0 : pw * v0;
                float p1 = v1 >= 0.f ? v1 : pw * v1;
                float p2 = v2 >= 0.f ? v2 : pw * v2;
                float p3 = v3 >= 0.f ? v3 : pw * v3;
                *(float2*)&out2[(size_t)(b * 128 + o0) * 1024 + n0 + ncol] =
                    make_float2(p0, p1);
                *(float2*)&out2[(size_t)(b * 128 + o0 + 8) * 1024 + n0 + ncol] =
                    make_float2(p2, p3);
                *(float2*)&prelu_s[o0 * 128 + ncol] = make_float2(p0, p1);
                *(float2*)&prelu_s[(o0 + 8) * 128 + ncol] = make_float2(p2, p3);
            }
        __syncthreads();

        {
            float r = __ldg(b_read);
            for (int o = 0; o < 64; o++)
                r = fmaf(Wr_s[o], prelu_s[o * 128 + tid], r);
            for (int c = 0; c < 64; c++)
                r = fmaf(Wr_s[64 + c],
                         h[(size_t)(b * 64 + c) * 1024 + n0 + tid], r);
            out[(size_t)b * 1024 + n0 + tid] = r;
        }
        __syncthreads();
    }
}

// ---------------------------------------------------------------------------
extern "C" void kernel_launch(void* const* d_in, const int* in_sizes, int n_in,
                              void* d_out, int out_size)
{
    const float* x      = (const float*)d_in[0];
    const float* m      = (const float*)d_in[1];
    const float* u      = (const float*)d_in[2];
    const float* h      = (const float*)d_in[3];
    const float* adj    = (const float*)d_in[4];
    const float* W_in   = (const float*)d_in[5];
    const float* b_in   = (const float*)d_in[6];
    const float* W_gc   = (const float*)d_in[7];
    const float* b_gc   = (const float*)d_in[8];
    const float* W_out  = (const float*)d_in[9];
    const float* b_out  = (const float*)d_in[10];
    const float* W_read = (const float*)d_in[11];
    const float* b_read = (const float*)d_in[12];
    const float* prelu  = (const float*)d_in[13];
    float* out = (float*)d_out;

    cudaFuncSetAttribute(k_gemm_fused, cudaFuncAttributeMaxDynamicSharedMemorySize, GDYN);
    cudaFuncSetAttribute(k_y_mma, cudaFuncAttributeMaxDynamicSharedMemorySize, YDYN);

    k_prep<<<2083, 256>>>(adj, W_in, b_in, W_gc);
    k_y_mma<<<1024, 128, YDYN>>>(x, m, u, h);
    dim3 g(Nn / BN, (Bb * DMdim) / BM);   // (8, 64) = 512 CTAs
    k_gemm_fused<<<g, 128, GDYN>>>(b_gc, h, W_out, b_out, W_read, b_read, prelu, out);
}